// round 15
// baseline (speedup 1.0000x reference)
#include <cuda_runtime.h>
#include <cuda_bf16.h>
#include <cstdint>

#define DEV_INLINE __device__ __forceinline__

constexpr int Bb = 8;
constexpr int Nn = 4096;

// ---------------- static device scratch (no allocation) ----------------
__device__ unsigned g_hpk_hi[Bb * (Nn/2) * 64];   // h bf16, node-pair packed (4 MB)
__device__ unsigned g_cnt[Bb];                     // per-batch arrival counters (monotonic)

DEV_INLINE unsigned packbf(float a, float b) {
    __nv_bfloat162 t2 = __floats2bfloat162_rn(a, b);
    return *reinterpret_cast<unsigned*>(&t2);
}

DEV_INLINE void mma_bf16(float* c, const unsigned* a, const unsigned* b) {
    asm volatile(
        "mma.sync.aligned.m16n8k16.row.col.f32.bf16.bf16.f32 "
        "{%0,%1,%2,%3}, {%4,%5,%6,%7}, {%8,%9}, {%0,%1,%2,%3};\n"
        : "+f"(c[0]), "+f"(c[1]), "+f"(c[2]), "+f"(c[3])
        : "r"(a[0]), "r"(a[1]), "r"(a[2]), "r"(a[3]), "r"(b[0]), "r"(b[1]));
}

// bf16 half of a packed pair -> fp32 (exact)
DEV_INLINE float bfhalf(unsigned u, int hi) {
    return __uint_as_float(hi ? (u & 0xffff0000u) : (u << 16));
}

// ============================================================================
// Fused kernel: phase 1 computes this CTA's 64x64 h tile (h = x·W) and
// publishes it; per-batch epoch-counter sync; phase 2 = R14 GEMM verbatim.
// ============================================================================
constexpr int A_ROWSTR = 40;                   // floats per A row (32 + 8 pad)
constexpr int A_STAGE  = 64 * A_ROWSTR;        // 2560 u32
constexpr int B_STR    = 72;                   // u32 per B kpair row
constexpr int B_STAGE  = 16 * B_STR;           // 1152 u32
constexpr int STAGES   = 3;
constexpr int OFF_A  = 0;
constexpr int OFF_B  = STAGES * A_STAGE;              // 7680
constexpr int OFF_RS = OFF_B + STAGES * B_STAGE;      // 11136 (64 floats)
constexpr int OFF_RI = OFF_RS + 64;                   // 11200 (64 floats)
constexpr int SMEM_U32 = OFF_RI + 64;                 // 11264
constexpr int SMEM_BYTES = SMEM_U32 * 4;              // 45056
// phase-1 W region: 64*72 = 4608 u32 at OFF_A (A stages are dead until GEMM)

DEV_INLINE void cp16pf(uint32_t saddr, const void* gptr) {   // +256B L2 prefetch
    asm volatile("cp.async.cg.shared.global.L2::256B [%0], [%1], 16;\n"
                 :: "r"(saddr), "l"(gptr));
}
DEV_INLINE void cp16(uint32_t saddr, const void* gptr) {
    asm volatile("cp.async.cg.shared.global [%0], [%1], 16;\n"
                 :: "r"(saddr), "l"(gptr));
}
DEV_INLINE void cp_commit() { asm volatile("cp.async.commit_group;\n"); }
DEV_INLINE void cp_wait1()  { asm volatile("cp.async.wait_group 1;\n"); }
DEV_INLINE void cp_wait0()  { asm volatile("cp.async.wait_group 0;\n"); }

__global__ void __launch_bounds__(256, 4)
spconv_fused_kernel(const float* __restrict__ x,   const float* __restrict__ adj,
                    const float* __restrict__ wgt, const float* __restrict__ bias,
                    float* __restrict__ out)
{
    extern __shared__ unsigned sm[];
    const uint32_t smb = (uint32_t)__cvta_generic_to_shared(sm);

    const int t    = threadIdx.x;
    const int lane = t & 31, warp = t >> 5;
    const int g = lane >> 2, tg = lane & 3;
    const int wrow = warp >> 1, wcol = warp & 1;     // 4 x 2 warp grid
    const int bx = blockIdx.x, b = blockIdx.y;
    const int node0 = bx * 64;

    // ======================= phase 1: h tile =======================
    // W -> smem bf16 kpair layout (stride 72 u32), in the A-stage region
    for (int idx = t; idx < 64 * 64; idx += 256) {
        int kp = idx >> 6, j = idx & 63;
        int ka = kp * 2, m = ka >> 5, a = ka & 31, p = j >> 4, w = j & 15;
        const float* wp = wgt + (((m * 4 + p) * 32 + a) << 4) + w;
        sm[kp * 72 + j] = packbf(wp[0], wp[16]);     // k = a, a+1
    }
    __syncthreads();

    {
        float acch[4][4];
#pragma unroll
        for (int nf = 0; nf < 4; nf++)
#pragma unroll
            for (int i = 0; i < 4; i++) acch[nf][i] = 0.f;

        const float* xr0 = x + ((size_t)(b * Nn) + node0 + wrow * 16 + g) * 128;
        const float* xr8 = xr0 + 8 * 128;
#pragma unroll
        for (int ks = 0; ks < 8; ks++) {
            const int k0 = ks * 16 + 2 * tg;
            float2 a0 = *(const float2*)(xr0 + k0);
            float2 a1 = *(const float2*)(xr8 + k0);
            float2 a2 = *(const float2*)(xr0 + k0 + 8);
            float2 a3 = *(const float2*)(xr8 + k0 + 8);
            unsigned ah[4];
            ah[0] = packbf(a0.x, a0.y); ah[1] = packbf(a1.x, a1.y);
            ah[2] = packbf(a2.x, a2.y); ah[3] = packbf(a3.x, a3.y);
#pragma unroll
            for (int nf = 0; nf < 4; nf++) {
                unsigned bh[2];
                int n = wcol * 32 + nf * 8 + g;
                bh[0] = sm[(ks * 8 + tg) * 72 + n];
                bh[1] = sm[(ks * 8 + 4 + tg) * 72 + n];
                mma_bf16(acch[nf], ah, bh);
            }
        }

        // publish node-pair packed bf16 h (rows g & g+1 paired via shfl)
        unsigned* hpOut = g_hpk_hi + (size_t)b * 131072;
        const int rA = node0 + wrow * 16 + g;        // even when g even
        const int prA = rA >> 1, prB = prA + 4;
#pragma unroll
        for (int nf = 0; nf < 4; nf++) {
            float d0 = __shfl_xor_sync(0xffffffffu, acch[nf][0], 4);
            float d1 = __shfl_xor_sync(0xffffffffu, acch[nf][1], 4);
            float d2 = __shfl_xor_sync(0xffffffffu, acch[nf][2], 4);
            float d3 = __shfl_xor_sync(0xffffffffu, acch[nf][3], 4);
            if ((g & 1) == 0) {
                int j = wcol * 32 + nf * 8 + 2 * tg;
                *(uint2*)(hpOut + prA * 64 + j) =
                    make_uint2(packbf(acch[nf][0], d0), packbf(acch[nf][1], d1));
                *(uint2*)(hpOut + prB * 64 + j) =
                    make_uint2(packbf(acch[nf][2], d2), packbf(acch[nf][3], d3));
            }
        }
    }

    // ---- per-batch epoch sync (all 512 CTAs co-resident at 4/SM) ----
    __threadfence();
    if (t == 0) {
        unsigned old = atomicAdd(&g_cnt[b], 1u);
        unsigned target = (old / 64u) * 64u + 64u;
        unsigned v;
        do {
            asm volatile("ld.global.cg.u32 %0, [%1];" : "=r"(v) : "l"(g_cnt + b) : "memory");
            if ((int)(v - target) >= 0) break;
            asm volatile("nanosleep.u32 64;");
        } while (true);
        __threadfence();
    }
    __syncthreads();

    // ======================= phase 2: GEMM (R14 verbatim) =======================
    // A copy: thread row t>>2 (0..63), 32B chunk t&3 (coalesced)
    const int arow = t >> 2, achk = t & 3;
    const float* adj_base =
        adj + ((size_t)(b * Nn) + (size_t)node0 + arow) * Nn + achk * 8;
    const uint32_t sa_base = smb + (OFF_A + arow * A_ROWSTR + achk * 8) * 4;
    // B copy: kpair = t>>4, 4 u32 columns
    const int bkp = t >> 4, bn4 = (t & 15) * 4;
    const unsigned* hpH = g_hpk_hi + (size_t)b * 131072 + bkp * 64 + bn4;
    const uint32_t sb_base = smb + (OFF_B + bkp * B_STR + bn4) * 4;

    float acc[4][4];
#pragma unroll
    for (int nf = 0; nf < 4; nf++)
#pragma unroll
        for (int i = 0; i < 4; i++) acc[nf][i] = 0.f;

    float rsum0 = 0.f, rsum1 = 0.f;
    const int r0 = wrow * 16 + g;

    auto issue = [&](int kt, int s) {
        const float* ga = adj_base + (size_t)kt * 32;
        uint32_t sa = sa_base + s * (A_STAGE * 4);
        cp16pf(sa,      ga);
        cp16pf(sa + 16, ga + 4);
        cp16(sb_base + s * (B_STAGE * 4), hpH + (size_t)kt * 1024);
        cp_commit();
    };

    auto compute = [&](int s) {
        const float*    Af = (const float*)(sm + OFF_A + s * A_STAGE);
        const unsigned* Bh = sm + OFF_B + s * B_STAGE;
#pragma unroll
        for (int ks = 0; ks < 2; ks++) {
            unsigned bh[4][2];
#pragma unroll
            for (int nf = 0; nf < 4; nf++) {
                int n = wcol * 32 + nf * 8 + g;
                int k0 = (ks * 8 + tg) * B_STR + n;
                bh[nf][0] = Bh[k0];  bh[nf][1] = Bh[k0 + 4 * B_STR];
            }
            const int kb = ks * 16 + 2 * tg;
            float2 p0 = *(const float2*)(Af + (r0    ) * A_ROWSTR + kb);
            float2 p1 = *(const float2*)(Af + (r0 + 8) * A_ROWSTR + kb);
            float2 p2 = *(const float2*)(Af + (r0    ) * A_ROWSTR + kb + 8);
            float2 p3 = *(const float2*)(Af + (r0 + 8) * A_ROWSTR + kb + 8);
            if (wcol == 0) {
                rsum0 += (p0.x + p0.y) + (p2.x + p2.y);
                rsum1 += (p1.x + p1.y) + (p3.x + p3.y);
            }
            unsigned ah[4];
            ah[0] = packbf(p0.x, p0.y); ah[1] = packbf(p1.x, p1.y);
            ah[2] = packbf(p2.x, p2.y); ah[3] = packbf(p3.x, p3.y);
#pragma unroll
            for (int nf = 0; nf < 4; nf++)
                mma_bf16(acc[nf], ah, bh[nf]);
        }
    };

    // ---- 3-stage pipeline, one barrier per tile ----
    issue(0, 0);
    issue(1, 1);
    int s = 0, si = 2;
#pragma unroll 1
    for (int kt = 0; kt < 128; kt++) {
        if (kt >= 126) cp_wait0(); else cp_wait1();
        __syncthreads();
        compute(s);
        if (kt + 2 < 128) issue(kt + 2, si);
        else cp_commit();                 // keep group-count semantics in tail
        s  = (s  == STAGES - 1) ? 0 : s + 1;
        si = (si == STAGES - 1) ? 0 : si + 1;
    }

    // ---- rowsum -> rinv ----
    float* rs   = (float*)(sm + OFF_RS);
    float* rinv = (float*)(sm + OFF_RI);
    __syncthreads();
    if (wcol == 0) {
        rsum0 += __shfl_xor_sync(0xffffffffu, rsum0, 1);
        rsum0 += __shfl_xor_sync(0xffffffffu, rsum0, 2);
        rsum1 += __shfl_xor_sync(0xffffffffu, rsum1, 1);
        rsum1 += __shfl_xor_sync(0xffffffffu, rsum1, 2);
        if (tg == 0) { rs[r0] = rsum0; rs[r0 + 8] = rsum1; }
    }
    __syncthreads();
    if (t < 64) rinv[t] = 1.0f / (1.0f + rs[t]);   // +1 = self loop
    __syncthreads();

    // ---- epilogue: out = relu((S + h)*rinv) + bias; h from bf16 pairs ----
    const unsigned* hB = g_hpk_hi + (size_t)b * 131072;
    const int gr0 = node0 + r0;
    const int pr0 = gr0 >> 1;
    const int par = g & 1;
#pragma unroll
    for (int nf = 0; nf < 4; nf++) {
        int c  = wcol * 32 + nf * 8 + 2 * tg;
        float ri0 = rinv[r0], ri1 = rinv[r0 + 8];
        uint2 hv0 = *(const uint2*)(hB + pr0 * 64 + c);
        uint2 hv1 = *(const uint2*)(hB + (pr0 + 4) * 64 + c);
        size_t o0 = ((size_t)(b * Nn + gr0)) * 64 + c;
        size_t o1 = o0 + (size_t)8 * 64;
        float bz0 = __ldg(bias + c), bz1 = __ldg(bias + c + 1);
        float2 w0, w1;
        w0.x = fmaxf((acc[nf][0] + bfhalf(hv0.x, par)) * ri0, 0.f) + bz0;
        w0.y = fmaxf((acc[nf][1] + bfhalf(hv0.y, par)) * ri0, 0.f) + bz1;
        w1.x = fmaxf((acc[nf][2] + bfhalf(hv1.x, par)) * ri1, 0.f) + bz0;
        w1.y = fmaxf((acc[nf][3] + bfhalf(hv1.y, par)) * ri1, 0.f) + bz1;
        *(float2*)(out + o0) = w0;
        *(float2*)(out + o1) = w1;
    }
}

// ============================================================================
extern "C" void kernel_launch(void* const* d_in, const int* in_sizes, int n_in,
                              void* d_out, int out_size)
{
    const float* x    = (const float*)d_in[0];
    const float* adj  = (const float*)d_in[1];
    const float* wgt  = (const float*)d_in[2];
    const float* bias = (const float*)d_in[3];
    float* out = (float*)d_out;

    spconv_fused_kernel<<<dim3(64, 8), 256, SMEM_BYTES>>>(x, adj, wgt, bias, out);
}

// round 16
// speedup vs baseline: 1.0144x; 1.0144x over previous
#include <cuda_runtime.h>
#include <cuda_bf16.h>
#include <cstdint>

#define DEV_INLINE __device__ __forceinline__

constexpr int Bb = 8;
constexpr int Nn = 4096;

// ---------------- static device scratch (no allocation) ----------------
__device__ unsigned g_hpk_hi[Bb * (Nn/2) * 64];   // h bf16, node-pair packed (4 MB)

DEV_INLINE unsigned packbf(float a, float b) {
    __nv_bfloat162 t2 = __floats2bfloat162_rn(a, b);
    return *reinterpret_cast<unsigned*>(&t2);
}

DEV_INLINE void mma_bf16(float* c, const unsigned* a, const unsigned* b) {
    asm volatile(
        "mma.sync.aligned.m16n8k16.row.col.f32.bf16.bf16.f32 "
        "{%0,%1,%2,%3}, {%4,%5,%6,%7}, {%8,%9}, {%0,%1,%2,%3};\n"
        : "+f"(c[0]), "+f"(c[1]), "+f"(c[2]), "+f"(c[3])
        : "r"(a[0]), "r"(a[1]), "r"(a[2]), "r"(a[3]), "r"(b[0]), "r"(b[1]));
}

// bf16 half of a packed pair -> fp32 (exact)
DEV_INLINE float bfhalf(unsigned u, int hi) {
    return __uint_as_float(hi ? (u & 0xffff0000u) : (u << 16));
}

// ============================================================================
// Kernel 1 (v3): h[128-node tile, 64] = x_tile @ W. 256 thr / 8 warps, warp =
// 16 rows x 64 cols. x fragments direct from LDG (no smem, no ldsm); W in
// smem kpair layout; node-pair packing via shfl (no staging). R15-phase1 math.
// ============================================================================
__global__ void __launch_bounds__(256)
spconv_h_mma(const float* __restrict__ x, const float* __restrict__ wgt)
{
    __shared__ unsigned ws[64 * 72];     // W bf16 kpair layout (18.4 KB)
    const int t = threadIdx.x;
    const int lane = t & 31, warp = t >> 5;
    const int g = lane >> 2, tg = lane & 3;
    const int b = blockIdx.y;
    const int node0 = blockIdx.x * 128;

    // ---- W -> smem bf16 kpair (stride 72 u32) ----
    for (int idx = t; idx < 64 * 64; idx += 256) {
        int kp = idx >> 6, j = idx & 63;
        int ka = kp * 2, m = ka >> 5, a = ka & 31, p = j >> 4, w = j & 15;
        const float* wp = wgt + (((m * 4 + p) * 32 + a) << 4) + w;
        ws[kp * 72 + j] = packbf(wp[0], wp[16]);     // k = a, a+1
    }
    __syncthreads();

    float acch[8][4];
#pragma unroll
    for (int nf = 0; nf < 8; nf++)
#pragma unroll
        for (int i = 0; i < 4; i++) acch[nf][i] = 0.f;

    const float* xr0 = x + ((size_t)(b * Nn) + node0 + warp * 16 + g) * 128;
    const float* xr8 = xr0 + 8 * 128;
#pragma unroll
    for (int ks = 0; ks < 8; ks++) {
        const int k0 = ks * 16 + 2 * tg;
        float2 a0 = *(const float2*)(xr0 + k0);
        float2 a1 = *(const float2*)(xr8 + k0);
        float2 a2 = *(const float2*)(xr0 + k0 + 8);
        float2 a3 = *(const float2*)(xr8 + k0 + 8);
        unsigned ah[4];
        ah[0] = packbf(a0.x, a0.y); ah[1] = packbf(a1.x, a1.y);
        ah[2] = packbf(a2.x, a2.y); ah[3] = packbf(a3.x, a3.y);
#pragma unroll
        for (int nf = 0; nf < 8; nf++) {
            unsigned bh[2];
            int n = nf * 8 + g;
            bh[0] = ws[(ks * 8 + tg) * 72 + n];
            bh[1] = ws[(ks * 8 + 4 + tg) * 72 + n];
            mma_bf16(acch[nf], ah, bh);
        }
    }

    // ---- publish node-pair packed bf16 h (rows g & g+1 paired via shfl) ----
    unsigned* hpOut = g_hpk_hi + (size_t)b * 131072;
    const int rA = node0 + warp * 16 + g;
    const int prA = rA >> 1, prB = prA + 4;
#pragma unroll
    for (int nf = 0; nf < 8; nf++) {
        float d0 = __shfl_xor_sync(0xffffffffu, acch[nf][0], 4);
        float d1 = __shfl_xor_sync(0xffffffffu, acch[nf][1], 4);
        float d2 = __shfl_xor_sync(0xffffffffu, acch[nf][2], 4);
        float d3 = __shfl_xor_sync(0xffffffffu, acch[nf][3], 4);
        if ((g & 1) == 0) {
            int j = nf * 8 + 2 * tg;
            *(uint2*)(hpOut + prA * 64 + j) =
                make_uint2(packbf(acch[nf][0], d0), packbf(acch[nf][1], d1));
            *(uint2*)(hpOut + prB * 64 + j) =
                make_uint2(packbf(acch[nf][2], d2), packbf(acch[nf][3], d3));
        }
    }
}

// ============================================================================
// Kernel 2 (R14 verbatim): BK=32, 256 thr, warp tile 16x32, cp.async 3-stage
// + L2::256B prefetch on A, one barrier/tile, 4 CTAs/SM. Self-loop h from
// bf16 g_hpk_hi.
// ============================================================================
constexpr int A_ROWSTR = 40;                   // floats per A row (32 + 8 pad)
constexpr int A_STAGE  = 64 * A_ROWSTR;        // 2560 u32
constexpr int B_STR    = 72;                   // u32 per B kpair row
constexpr int B_STAGE  = 16 * B_STR;           // 1152 u32
constexpr int STAGES   = 3;
constexpr int OFF_A  = 0;
constexpr int OFF_B  = STAGES * A_STAGE;              // 7680
constexpr int OFF_RS = OFF_B + STAGES * B_STAGE;      // 11136 (64 floats)
constexpr int OFF_RI = OFF_RS + 64;                   // 11200 (64 floats)
constexpr int SMEM_U32 = OFF_RI + 64;                 // 11264
constexpr int SMEM_BYTES = SMEM_U32 * 4;              // 45056

DEV_INLINE void cp16pf(uint32_t saddr, const void* gptr) {   // +256B L2 prefetch
    asm volatile("cp.async.cg.shared.global.L2::256B [%0], [%1], 16;\n"
                 :: "r"(saddr), "l"(gptr));
}
DEV_INLINE void cp16(uint32_t saddr, const void* gptr) {
    asm volatile("cp.async.cg.shared.global [%0], [%1], 16;\n"
                 :: "r"(saddr), "l"(gptr));
}
DEV_INLINE void cp_commit() { asm volatile("cp.async.commit_group;\n"); }
DEV_INLINE void cp_wait1()  { asm volatile("cp.async.wait_group 1;\n"); }
DEV_INLINE void cp_wait0()  { asm volatile("cp.async.wait_group 0;\n"); }

__global__ void __launch_bounds__(256, 4)
spconv_gemm_kernel(const float* __restrict__ adj, const float* __restrict__ bias,
                   float* __restrict__ out)
{
    extern __shared__ unsigned sm[];
    const uint32_t smb = (uint32_t)__cvta_generic_to_shared(sm);

    const int t    = threadIdx.x;
    const int lane = t & 31, warp = t >> 5;
    const int g = lane >> 2, tg = lane & 3;
    const int wrow = warp >> 1, wcol = warp & 1;     // 4 x 2 warp grid
    const int bx = blockIdx.x, b = blockIdx.y;

    // A copy: thread row t>>2 (0..63), 32B chunk t&3 (coalesced)
    const int arow = t >> 2, achk = t & 3;
    const float* adj_base =
        adj + ((size_t)(b * Nn) + (size_t)bx * 64 + arow) * Nn + achk * 8;
    const uint32_t sa_base = smb + (OFF_A + arow * A_ROWSTR + achk * 8) * 4;
    // B copy: kpair = t>>4, 4 u32 columns
    const int bkp = t >> 4, bn4 = (t & 15) * 4;
    const unsigned* hpH = g_hpk_hi + (size_t)b * 131072 + bkp * 64 + bn4;
    const uint32_t sb_base = smb + (OFF_B + bkp * B_STR + bn4) * 4;

    float acc[4][4];
#pragma unroll
    for (int nf = 0; nf < 4; nf++)
#pragma unroll
        for (int i = 0; i < 4; i++) acc[nf][i] = 0.f;

    float rsum0 = 0.f, rsum1 = 0.f;
    const int r0 = wrow * 16 + g;

    auto issue = [&](int kt, int s) {
        const float* ga = adj_base + (size_t)kt * 32;
        uint32_t sa = sa_base + s * (A_STAGE * 4);
        cp16pf(sa,      ga);
        cp16pf(sa + 16, ga + 4);
        cp16(sb_base + s * (B_STAGE * 4), hpH + (size_t)kt * 1024);
        cp_commit();
    };

    auto compute = [&](int s) {
        const float*    Af = (const float*)(sm + OFF_A + s * A_STAGE);
        const unsigned* Bh = sm + OFF_B + s * B_STAGE;
#pragma unroll
        for (int ks = 0; ks < 2; ks++) {
            unsigned bh[4][2];
#pragma unroll
            for (int nf = 0; nf < 4; nf++) {
                int n = wcol * 32 + nf * 8 + g;
                int k0 = (ks * 8 + tg) * B_STR + n;
                bh[nf][0] = Bh[k0];  bh[nf][1] = Bh[k0 + 4 * B_STR];
            }
            const int kb = ks * 16 + 2 * tg;
            float2 p0 = *(const float2*)(Af + (r0    ) * A_ROWSTR + kb);
            float2 p1 = *(const float2*)(Af + (r0 + 8) * A_ROWSTR + kb);
            float2 p2 = *(const float2*)(Af + (r0    ) * A_ROWSTR + kb + 8);
            float2 p3 = *(const float2*)(Af + (r0 + 8) * A_ROWSTR + kb + 8);
            if (wcol == 0) {
                rsum0 += (p0.x + p0.y) + (p2.x + p2.y);
                rsum1 += (p1.x + p1.y) + (p3.x + p3.y);
            }
            unsigned ah[4];
            ah[0] = packbf(p0.x, p0.y); ah[1] = packbf(p1.x, p1.y);
            ah[2] = packbf(p2.x, p2.y); ah[3] = packbf(p3.x, p3.y);
#pragma unroll
            for (int nf = 0; nf < 4; nf++)
                mma_bf16(acc[nf], ah, bh[nf]);
        }
    };

    // ---- 3-stage pipeline, one barrier per tile ----
    issue(0, 0);
    issue(1, 1);
    int s = 0, si = 2;
#pragma unroll 1
    for (int kt = 0; kt < 128; kt++) {
        if (kt >= 126) cp_wait0(); else cp_wait1();
        __syncthreads();
        compute(s);
        if (kt + 2 < 128) issue(kt + 2, si);
        else cp_commit();                 // keep group-count semantics in tail
        s  = (s  == STAGES - 1) ? 0 : s + 1;
        si = (si == STAGES - 1) ? 0 : si + 1;
    }

    // ---- rowsum -> rinv ----
    float* rs   = (float*)(sm + OFF_RS);
    float* rinv = (float*)(sm + OFF_RI);
    __syncthreads();
    if (wcol == 0) {
        rsum0 += __shfl_xor_sync(0xffffffffu, rsum0, 1);
        rsum0 += __shfl_xor_sync(0xffffffffu, rsum0, 2);
        rsum1 += __shfl_xor_sync(0xffffffffu, rsum1, 1);
        rsum1 += __shfl_xor_sync(0xffffffffu, rsum1, 2);
        if (tg == 0) { rs[r0] = rsum0; rs[r0 + 8] = rsum1; }
    }
    __syncthreads();
    if (t < 64) rinv[t] = 1.0f / (1.0f + rs[t]);   // +1 = self loop
    __syncthreads();

    // ---- epilogue: out = relu((S + h)*rinv) + bias; h from bf16 pairs ----
    const unsigned* hB = g_hpk_hi + (size_t)b * 131072;
    const int gr0 = bx * 64 + r0;
    const int pr0 = gr0 >> 1;
    const int par = g & 1;
#pragma unroll
    for (int nf = 0; nf < 4; nf++) {
        int c  = wcol * 32 + nf * 8 + 2 * tg;
        float ri0 = rinv[r0], ri1 = rinv[r0 + 8];
        uint2 hv0 = *(const uint2*)(hB + pr0 * 64 + c);
        uint2 hv1 = *(const uint2*)(hB + (pr0 + 4) * 64 + c);
        size_t o0 = ((size_t)(b * Nn + gr0)) * 64 + c;
        size_t o1 = o0 + (size_t)8 * 64;
        float bz0 = __ldg(bias + c), bz1 = __ldg(bias + c + 1);
        float2 w0, w1;
        w0.x = fmaxf((acc[nf][0] + bfhalf(hv0.x, par)) * ri0, 0.f) + bz0;
        w0.y = fmaxf((acc[nf][1] + bfhalf(hv0.y, par)) * ri0, 0.f) + bz1;
        w1.x = fmaxf((acc[nf][2] + bfhalf(hv1.x, par)) * ri1, 0.f) + bz0;
        w1.y = fmaxf((acc[nf][3] + bfhalf(hv1.y, par)) * ri1, 0.f) + bz1;
        *(float2*)(out + o0) = w0;
        *(float2*)(out + o1) = w1;
    }
}

// ============================================================================
extern "C" void kernel_launch(void* const* d_in, const int* in_sizes, int n_in,
                              void* d_out, int out_size)
{
    const float* x    = (const float*)d_in[0];
    const float* adj  = (const float*)d_in[1];
    const float* wgt  = (const float*)d_in[2];
    const float* bias = (const float*)d_in[3];
    float* out = (float*)d_out;

    spconv_h_mma<<<dim3(32, 8), 256>>>(x, wgt);
    spconv_gemm_kernel<<<dim3(64, 8), 256, SMEM_BYTES>>>(adj, bias, out);
}